// round 5
// baseline (speedup 1.0000x reference)
#include <cuda_runtime.h>
#include <cuda_bf16.h>
#include <math.h>

#define TN     256
#define DDIM   6
#define NEXP   540
#define NGEO   20
#define KPHI   27
#define NPROB  560          // 540 experts + 20 baselines
#define NTEST  1024
#define PACK   32896        // 256*257/2
#define JIT    1e-4f

// ---------------- static device scratch ----------------
__device__ int   g_cnt[NPROB];                    // points per problem
__device__ int   g_pts[(size_t)NPROB * NTEST];    // bucket lists
__device__ int   g_route_e[NTEST];
__device__ float g_mu_e[NTEST],  g_var_e[NTEST],  g_prior_e[NTEST];
__device__ float g_mu_b[NTEST],  g_var_b[NTEST],  g_prior_b[NTEST];

__device__ __forceinline__ int cpidx(int j) { return j * TN - ((j * (j - 1)) >> 1); }

// ---------------- kernel 0: clear counts ----------------
__global__ void k_zero() {
    int i = blockIdx.x * blockDim.x + threadIdx.x;
    if (i < NPROB) g_cnt[i] = 0;
}

// ---------------- kernel 1: routing + bucket build ----------------
__global__ void k_route(const float* __restrict__ Xt,
                        const float* __restrict__ smean, const float* __restrict__ sscale,
                        const float* __restrict__ gm,    const float* __restrict__ glv,
                        const float* __restrict__ glw,
                        const float* __restrict__ pm,    const float* __restrict__ plv,
                        const float* __restrict__ plw,
                        const int*   __restrict__ nmask)
{
    int n = blockIdx.x * blockDim.x + threadIdx.x;
    if (n >= NTEST) return;
    float xs[DDIM];
#pragma unroll
    for (int d = 0; d < DDIM; ++d) xs[d] = (Xt[n * DDIM + d] - smean[d]) / sscale[d];

    float best = -3e38f; int gb = 0;
    for (int gi = 0; gi < NGEO; ++gi) {
        float acc = 0.f;
#pragma unroll
        for (int d = 0; d < DDIM; ++d) {
            float lv = glv[gi * DDIM + d];
            float t  = xs[d] - gm[gi * DDIM + d];
            acc += lv + t * t * expf(-lv);
        }
        float lp = glw[gi] - 0.5f * acc;
        if (lp > best) { best = lp; gb = gi; }
    }
    float bestp = -3e38f; int kb = 0;
    for (int kk = 0; kk < KPHI; ++kk) {
        int base = (gb * KPHI + kk) * DDIM;
        float acc = 0.f;
#pragma unroll
        for (int d = 0; d < DDIM; ++d) {
            float lv = plv[base + d];
            float t  = xs[d] - pm[base + d];
            acc += lv + t * t * expf(-lv);
        }
        float lp = plw[gb * KPHI + kk] - 0.5f * acc;
        if (lp > bestp) { bestp = lp; kb = kk; }
    }
    int e = gb * KPHI + kb;
    g_route_e[n] = e;
    if (nmask[e] != 0) {
        int pos = atomicAdd(&g_cnt[e], 1);
        g_pts[(size_t)e * NTEST + pos] = n;
    }
    int pb = NEXP + gb;
    int pos2 = atomicAdd(&g_cnt[pb], 1);
    g_pts[(size_t)pb * NTEST + pos2] = n;
}

// ---------------- kernel 2: build K, Cholesky, Dinv, w-solve, FUSED prediction ----------------
// smem (floats): sA[PACK] | sXp[2048] | sPan[2048] | sW[256] | sId[256] | sDinv[8192] | sZ[4096]
#define SMEM_FLOATS (PACK + 2048 + 2048 + 256 + 256 + 8192 + 4096)

__global__ void __launch_bounds__(512, 1) k_factor(
    const float* __restrict__ Xt,
    const float* __restrict__ X_exp,  const float* __restrict__ Y_exp,
    const float* __restrict__ X_base, const float* __restrict__ Y_base,
    const float* __restrict__ lls_e, const float* __restrict__ los_e, const float* __restrict__ lno_e,
    const float* __restrict__ lls_b, const float* __restrict__ los_b, const float* __restrict__ lno_b)
{
    int b = blockIdx.x;
    int cnt = g_cnt[b];
    if (cnt == 0) return;

    extern __shared__ float sm[];
    float* sA    = sm;
    float* sXp   = sA    + PACK;     // X padded [256][8]
    float* sPan  = sXp   + 2048;     // panel rows [256][8]
    float* sW    = sPan  + 2048;     // y -> w = L^-1 y
    float* sId   = sW    + 256;      // 1/diag
    float* sDinv = sId   + 256;      // [tile][s][r] 8*32*32
    float* sZ    = sDinv + 8192;     // per-warp z [16][256]

    int tid  = threadIdx.x;
    int wid  = tid >> 5;
    int lane = tid & 31;

    const float* Xs; const float* Ys; float lls, los, lno;
    if (b < NEXP) {
        Xs = X_exp + (size_t)b * TN * DDIM;  Ys = Y_exp + b * TN;
        lls = lls_e[b]; los = los_e[b]; lno = lno_e[b];
    } else {
        int gb = b - NEXP;
        Xs = X_base + (size_t)gb * TN * DDIM; Ys = Y_base + gb * TN;
        lls = lls_b[gb]; los = los_b[gb]; lno = lno_b[gb];
    }
    float ls2 = expf(2.f * lls);
    float osv = expf(los);
    float nv  = expf(lno) + JIT;
    float c0  = -0.5f / ls2;

    // load X padded + y
    if (tid < TN) {
        int i = tid;
        float v[8];
#pragma unroll
        for (int d = 0; d < DDIM; ++d) v[d] = Xs[i * DDIM + d];
        v[6] = 0.f; v[7] = 0.f;
        float4* dst = (float4*)&sXp[i * 8];
        dst[0] = make_float4(v[0], v[1], v[2], v[3]);
        dst[1] = make_float4(v[4], v[5], v[6], v[7]);
        sW[i] = Ys[i];
    }
    __syncthreads();

    // ---- build K (packed column-major lower) ----
    {
        int row  = tid & 255;
        int half = tid >> 8;
        const float4* X4 = (const float4*)sXp;
        float4 xi0 = X4[row * 2], xi1 = X4[row * 2 + 1];
        int jmid = (row + 1) >> 1;
        int jlo = half ? jmid : 0;
        int jhi = half ? (row + 1) : jmid;
        int idx = cpidx(jlo) + row - jlo;
        for (int j = jlo; j < jhi; ++j) {
            float4 xj0 = X4[j * 2], xj1 = X4[j * 2 + 1];
            float t0 = xi0.x - xj0.x, t1 = xi0.y - xj0.y, t2 = xi0.z - xj0.z, t3 = xi0.w - xj0.w;
            float t4 = xi1.x - xj1.x, t5 = xi1.y - xj1.y;
            float d2 = t0*t0 + t1*t1 + t2*t2 + t3*t3 + t4*t4 + t5*t5;
            float kv = (j == row) ? (osv + nv) : (osv * __expf(c0 * d2));
            sA[idx] = kv;
            idx += 255 - j;
        }
    }
    __syncthreads();

    const float4* pan4 = (const float4*)sPan;

    // ---- blocked Cholesky, panel width 8 ----
    for (int q = 0; q < 32; ++q) {
        int j0   = q * 8;
        int base = j0 + 8;
        int R    = TN - base;

        if (tid < TN) {
            float Ld[8][8];
            float dinv[8];
#pragma unroll
            for (int c = 0; c < 8; ++c) {
                int bidx = cpidx(j0 + c);
#pragma unroll
                for (int r = 0; r < 8; ++r)
                    if (r >= c) Ld[r][c] = sA[bidx + (r - c)];
            }
#pragma unroll
            for (int c = 0; c < 8; ++c) {
                float dsq = Ld[c][c];
#pragma unroll
                for (int p = 0; p < 8; ++p) if (p < c) dsq -= Ld[c][p] * Ld[c][p];
                float dl = sqrtf(dsq);
                Ld[c][c] = dl;
                float inv = 1.0f / dl;
                dinv[c] = inv;
#pragma unroll
                for (int r = 0; r < 8; ++r) {
                    if (r > c) {
                        float v = Ld[r][c];
#pragma unroll
                        for (int p = 0; p < 8; ++p) if (p < c) v -= Ld[r][p] * Ld[c][p];
                        Ld[r][c] = v * inv;
                    }
                }
            }
            if (tid < R) {
                int i = base + tid;
                float a[8];
#pragma unroll
                for (int c = 0; c < 8; ++c) a[c] = sA[cpidx(j0 + c) + (i - (j0 + c))];
#pragma unroll
                for (int c = 0; c < 8; ++c) {
                    float v = a[c];
#pragma unroll
                    for (int p = 0; p < 8; ++p) if (p < c) v -= a[p] * Ld[c][p];
                    a[c] = v * dinv[c];
                }
#pragma unroll
                for (int c = 0; c < 8; ++c) sA[cpidx(j0 + c) + (i - (j0 + c))] = a[c];
                float4* sp = (float4*)&sPan[tid * 8];
                sp[0] = make_float4(a[0], a[1], a[2], a[3]);
                sp[1] = make_float4(a[4], a[5], a[6], a[7]);
            }
#pragma unroll
            for (int r = 0; r < 8; ++r) {
                if (tid == r) {
#pragma unroll
                    for (int c = 0; c < 8; ++c)
                        if (c <= r) sA[cpidx(j0 + c) + (r - c)] = Ld[r][c];
                }
            }
        }
        __syncthreads();

        // ---- SYRK: warp per 8-row tile, panel rows in registers ----
        if (R > 0) {
            int nt = (R + 7) >> 3;
            for (int rt = wid; rt < nt; rt += 16) {
                int r0 = rt << 3;
                float4 pi0[8], pi1[8];
#pragma unroll
                for (int rr = 0; rr < 8; ++rr) {
                    if (r0 + rr < R) {
                        pi0[rr] = pan4[(r0 + rr) * 2];
                        pi1[rr] = pan4[(r0 + rr) * 2 + 1];
                    } else {
                        pi0[rr] = make_float4(0.f, 0.f, 0.f, 0.f);
                        pi1[rr] = make_float4(0.f, 0.f, 0.f, 0.f);
                    }
                }
                int rmax = min(r0 + 7, R - 1);
                for (int kb = 0; kb <= rmax; kb += 32) {
                    int kk = kb + lane;
                    float4 q0 = make_float4(0.f, 0.f, 0.f, 0.f);
                    float4 q1 = q0;
                    if (kk <= rmax) {
                        q0 = pan4[kk * 2];
                        q1 = pan4[kk * 2 + 1];
                    }
                    int c = base + kk;
                    int cbase = c * TN - ((c * (c - 1)) >> 1);
#pragma unroll
                    for (int rr = 0; rr < 8; ++rr) {
                        int rho = r0 + rr;
                        if (kk <= rho && rho < R) {
                            int idx = cbase + (rho - kk);
                            float v = sA[idx];
                            v -= pi0[rr].x*q0.x + pi0[rr].y*q0.y + pi0[rr].z*q0.z + pi0[rr].w*q0.w
                               + pi1[rr].x*q1.x + pi1[rr].y*q1.y + pi1[rr].z*q1.z + pi1[rr].w*q1.w;
                            sA[idx] = v;
                        }
                    }
                }
            }
        }
        __syncthreads();
    }

    // ---- inverse diagonal ----
    if (tid < TN) sId[tid] = 1.0f / sA[cpidx(tid)];
    __syncthreads();

    // ---- epilogue: warp0 w-solve | warps1-8 Dinv (to smem) ----
    if (wid == 0) {
#pragma unroll 1
        for (int T = 0; T < 8; ++T) {
            int r = 32 * T + lane;
            float acc = sW[r];
            int lim = 32 * T;
            float a0 = 0.f, a1 = 0.f, a2 = 0.f, a3 = 0.f;
            int idx = r;
            for (int c = 0; c < lim; c += 4) {
                float z0 = sW[c], z1 = sW[c+1], z2 = sW[c+2], z3 = sW[c+3];
                float l0 = sA[idx]; idx += 255 - c;
                float l1 = sA[idx]; idx += 254 - c;
                float l2 = sA[idx]; idx += 253 - c;
                float l3 = sA[idx]; idx += 252 - c;
                a0 += l0 * z0; a1 += l1 * z1; a2 += l2 * z2; a3 += l3 * z3;
            }
            acc -= (a0 + a1) + (a2 + a3);
            float invv = sId[r];
            int cb = 32 * T;
            float myz = 0.f;
#pragma unroll
            for (int s = 0; s < 32; ++s) {
                float zc = __shfl_sync(0xffffffffu, acc, s) * __shfl_sync(0xffffffffu, invv, s);
                if (lane == s) myz = zc;
                if (lane > s) acc -= sA[cpidx(cb + s) + (lane - s)] * zc;
            }
            sW[r] = myz;
            __syncwarp();
        }
    } else if (wid <= 8) {
        // Dinv: warp handles diag tile t; lane = RHS column s. L loads warp-uniform.
        int t = wid - 1;
        int s = lane;
        int c0t = 32 * t;
        float x[32];
#pragma unroll
        for (int r = 0; r < 32; ++r) {
            float sum = 0.f;
#pragma unroll
            for (int k = 0; k < 32; ++k) {
                if (k < r) sum += sA[cpidx(c0t + k) + (r - k)] * x[k];
            }
            float ivr = sId[c0t + r];
            x[r] = (r == s) ? ivr : -sum * ivr;
        }
        float* dst = sDinv + t * 1024 + s * 32;
#pragma unroll
        for (int r = 0; r < 32; ++r) dst[r] = x[r];
    }
    __syncthreads();

    // ---- FUSED prediction: one warp per routed point, L/Dinv/w in smem ----
    const int* pts = g_pts + (size_t)b * NTEST;
    float* z = sZ + wid * TN;

    for (int pi = wid; pi < cnt; pi += 16) {
        int n = pts[pi];
        float xt0 = Xt[n*DDIM+0], xt1 = Xt[n*DDIM+1], xt2 = Xt[n*DDIM+2];
        float xt3 = Xt[n*DDIM+3], xt4 = Xt[n*DDIM+4], xt5 = Xt[n*DDIM+5];

        float qq = 0.f, mu = 0.f;
#pragma unroll 1
        for (int T = 0; T < 8; ++T) {
            int r  = 32 * T + lane;
            int cb = 32 * T;
            // k* entry for row r
            float4 x0 = ((const float4*)&sXp[r * 8])[0];
            float4 x1 = ((const float4*)&sXp[r * 8])[1];
            float t0 = xt0 - x0.x, t1 = xt1 - x0.y, t2 = xt2 - x0.z;
            float t3 = xt3 - x0.w, t4 = xt4 - x1.x, t5 = xt5 - x1.y;
            float d2 = t0*t0 + t1*t1 + t2*t2 + t3*t3 + t4*t4 + t5*t5;
            float acc = osv * __expf(c0 * d2);

            // GEMV vs previous z (smem L, conflict-free)
            float a0 = 0.f, a1 = 0.f, a2 = 0.f, a3 = 0.f;
            int idx = r;
#pragma unroll 2
            for (int c = 0; c < cb; c += 4) {
                float z0 = z[c], z1 = z[c+1], z2 = z[c+2], z3 = z[c+3];
                float l0 = sA[idx]; idx += 255 - c;
                float l1 = sA[idx]; idx += 254 - c;
                float l2 = sA[idx]; idx += 253 - c;
                float l3 = sA[idx]; idx += 252 - c;
                a0 += l0 * z0; a1 += l1 * z1; a2 += l2 * z2; a3 += l3 * z3;
            }
            acc -= (a0 + a1) + (a2 + a3);

            // v_tile = Dinv_T * acc
            const float* Dt = sDinv + T * 1024;
            float v0 = 0.f, v1 = 0.f, v2 = 0.f, v3 = 0.f;
#pragma unroll
            for (int s = 0; s < 32; s += 4) {
                float d0 = Dt[(s+0) * 32 + lane];
                float d1 = Dt[(s+1) * 32 + lane];
                float dv2 = Dt[(s+2) * 32 + lane];
                float d3 = Dt[(s+3) * 32 + lane];
                float b0 = __shfl_sync(0xffffffffu, acc, s+0);
                float b1 = __shfl_sync(0xffffffffu, acc, s+1);
                float b2 = __shfl_sync(0xffffffffu, acc, s+2);
                float b3 = __shfl_sync(0xffffffffu, acc, s+3);
                v0 += d0 * b0; v1 += d1 * b1; v2 += dv2 * b2; v3 += d3 * b3;
            }
            float v = (v0 + v1) + (v2 + v3);
            z[r] = v;
            qq += v * v;
            mu += v * sW[r];
            __syncwarp();
        }

#pragma unroll
        for (int o = 16; o; o >>= 1) {
            mu += __shfl_xor_sync(0xffffffffu, mu, o);
            qq += __shfl_xor_sync(0xffffffffu, qq, o);
        }
        if (lane == 0) {
            float var = fmaxf(osv - qq, JIT) + nv;
            float prior = osv + nv;
            if (b < NEXP) { g_mu_e[n] = mu; g_var_e[n] = var; g_prior_e[n] = prior; }
            else          { g_mu_b[n] = mu; g_var_b[n] = var; g_prior_b[n] = prior; }
        }
    }
}

// ---------------- kernel 3: rBCM combine ----------------
__global__ void k_combine(const int* __restrict__ nmask, float* __restrict__ out)
{
    int n = blockIdx.x * blockDim.x + threadIdx.x;
    if (n >= NTEST) return;
    int e = g_route_e[n];
    bool isnull = (nmask[e] == 0);
    float mub = g_mu_b[n], varb = g_var_b[n], prb = g_prior_b[n];
    float bb = fmaxf(0.5f * (logf(prb) - logf(varb)), 0.f);
    float be = 0.f, te = 0.f, me = 0.f;
    if (!isnull) {
        float mue = g_mu_e[n], vare = g_var_e[n], pre = g_prior_e[n];
        be = fmaxf(0.5f * (logf(pre) - logf(vare)), 0.f);
        te = be / vare;
        me = be * mue / vare;
    }
    float prec = te + bb / varb + (1.f - be - bb) / prb;
    prec = fmaxf(prec, 1e-6f);
    float mean = (me + bb * mub / varb) / prec;
    out[n] = mean;
    out[NTEST + n] = 1.f / prec;
}

// ---------------- launch ----------------
extern "C" void kernel_launch(void* const* d_in, const int* in_sizes, int n_in,
                              void* d_out, int out_size)
{
    const float* X_test   = (const float*)d_in[0];
    const float* X_exp    = (const float*)d_in[1];
    const float* Y_exp    = (const float*)d_in[2];
    const float* X_base   = (const float*)d_in[3];
    const float* Y_base   = (const float*)d_in[4];
    const float* lls_e    = (const float*)d_in[5];
    const float* los_e    = (const float*)d_in[6];
    const float* lno_e    = (const float*)d_in[7];
    const float* lls_b    = (const float*)d_in[8];
    const float* los_b    = (const float*)d_in[9];
    const float* lno_b    = (const float*)d_in[10];
    const float* smean    = (const float*)d_in[11];
    const float* sscale   = (const float*)d_in[12];
    const float* gm       = (const float*)d_in[13];
    const float* glv      = (const float*)d_in[14];
    const float* glw      = (const float*)d_in[15];
    const float* pm       = (const float*)d_in[16];
    const float* plv      = (const float*)d_in[17];
    const float* plw      = (const float*)d_in[18];
    const int*   nmask    = (const int*)d_in[19];
    float* out = (float*)d_out;

    static_assert(SMEM_FLOATS * 4 <= 232448, "smem");
    cudaFuncSetAttribute(k_factor, cudaFuncAttributeMaxDynamicSharedMemorySize,
                         SMEM_FLOATS * 4);

    k_zero<<<(NPROB + 255) / 256, 256>>>();
    k_route<<<(NTEST + 255) / 256, 256>>>(X_test, smean, sscale, gm, glv, glw,
                                          pm, plv, plw, nmask);
    k_factor<<<NPROB, 512, SMEM_FLOATS * 4>>>(X_test, X_exp, Y_exp, X_base, Y_base,
                                              lls_e, los_e, lno_e,
                                              lls_b, los_b, lno_b);
    k_combine<<<(NTEST + 255) / 256, 256>>>(nmask, out);
}

// round 6
// speedup vs baseline: 1.2769x; 1.2769x over previous
#include <cuda_runtime.h>
#include <cuda_bf16.h>
#include <math.h>

#define TN     256
#define DDIM   6
#define NEXP   540
#define NGEO   20
#define KPHI   27
#define NPROB  560          // 540 experts + 20 baselines
#define NTEST  1024
#define PACK   32896        // 256*257/2
#define JIT    1e-4f

// ---------------- static device scratch ----------------
__device__ float g_L[(size_t)NPROB * PACK];           // packed column-major lower L
__device__ float g_w[NPROB * TN];                     // w = L^-1 y
__device__ float g_dinv[(size_t)NPROB * 8 * 32 * 32]; // per-tile 32x32 diag-block inverses [tile][s][r]
__device__ int   g_cnt[NPROB];                        // routed points per problem
__device__ int   g_pts[(size_t)NPROB * NTEST];        // bucket lists
__device__ int   g_route_e[NTEST];
__device__ float g_mu_e[NTEST],  g_var_e[NTEST],  g_prior_e[NTEST];
__device__ float g_mu_b[NTEST],  g_var_b[NTEST],  g_prior_b[NTEST];

__device__ __forceinline__ int cpidx(int j) { return j * TN - ((j * (j - 1)) >> 1); }

// ---------------- kernel 0: clear counts ----------------
__global__ void k_zero() {
    int i = blockIdx.x * blockDim.x + threadIdx.x;
    if (i < NPROB) g_cnt[i] = 0;
}

// ---------------- kernel 1: routing + bucket build ----------------
__global__ void k_route(const float* __restrict__ Xt,
                        const float* __restrict__ smean, const float* __restrict__ sscale,
                        const float* __restrict__ gm,    const float* __restrict__ glv,
                        const float* __restrict__ glw,
                        const float* __restrict__ pm,    const float* __restrict__ plv,
                        const float* __restrict__ plw,
                        const int*   __restrict__ nmask)
{
    int n = blockIdx.x * blockDim.x + threadIdx.x;
    if (n >= NTEST) return;
    float xs[DDIM];
#pragma unroll
    for (int d = 0; d < DDIM; ++d) xs[d] = (Xt[n * DDIM + d] - smean[d]) / sscale[d];

    float best = -3e38f; int gb = 0;
    for (int gi = 0; gi < NGEO; ++gi) {
        float acc = 0.f;
#pragma unroll
        for (int d = 0; d < DDIM; ++d) {
            float lv = glv[gi * DDIM + d];
            float t  = xs[d] - gm[gi * DDIM + d];
            acc += lv + t * t * expf(-lv);
        }
        float lp = glw[gi] - 0.5f * acc;
        if (lp > best) { best = lp; gb = gi; }
    }
    float bestp = -3e38f; int kb = 0;
    for (int kk = 0; kk < KPHI; ++kk) {
        int base = (gb * KPHI + kk) * DDIM;
        float acc = 0.f;
#pragma unroll
        for (int d = 0; d < DDIM; ++d) {
            float lv = plv[base + d];
            float t  = xs[d] - pm[base + d];
            acc += lv + t * t * expf(-lv);
        }
        float lp = plw[gb * KPHI + kk] - 0.5f * acc;
        if (lp > bestp) { bestp = lp; kb = kk; }
    }
    int e = gb * KPHI + kb;
    g_route_e[n] = e;
    if (nmask[e] != 0) {
        int pos = atomicAdd(&g_cnt[e], 1);
        g_pts[(size_t)e * NTEST + pos] = n;
    }
    int pb = NEXP + gb;
    int pos2 = atomicAdd(&g_cnt[pb], 1);
    g_pts[(size_t)pb * NTEST + pos2] = n;
}

// ---------------- kernel 2: build K, blocked Cholesky, Dinv, w-solve, export ----------------
// smem (floats): sA[PACK] | sXp[256*8] | sPan[256*8] | sW[256]
#define SMEM_FLOATS (PACK + TN*8 + TN*8 + TN)

__global__ void __launch_bounds__(512, 1) k_factor(
    const float* __restrict__ X_exp,  const float* __restrict__ Y_exp,
    const float* __restrict__ X_base, const float* __restrict__ Y_base,
    const float* __restrict__ lls_e, const float* __restrict__ los_e, const float* __restrict__ lno_e,
    const float* __restrict__ lls_b, const float* __restrict__ los_b, const float* __restrict__ lno_b)
{
    int b = blockIdx.x;
    if (g_cnt[b] == 0) return;

    extern __shared__ float sm[];
    float* sA   = sm;
    float* sXp  = sA + PACK;       // X padded [256][8]; later reused for inv-diag
    float* sPan = sXp + TN * 8;    // panel rows [256][8]
    float* sW   = sPan + TN * 8;   // y -> w

    int tid  = threadIdx.x;
    int wid  = tid >> 5;
    int lane = tid & 31;

    const float* Xs; const float* Ys; float lls, los, lno;
    if (b < NEXP) {
        Xs = X_exp + (size_t)b * TN * DDIM;  Ys = Y_exp + b * TN;
        lls = lls_e[b]; los = los_e[b]; lno = lno_e[b];
    } else {
        int gb = b - NEXP;
        Xs = X_base + (size_t)gb * TN * DDIM; Ys = Y_base + gb * TN;
        lls = lls_b[gb]; los = los_b[gb]; lno = lno_b[gb];
    }
    float ls2 = expf(2.f * lls);
    float osv = expf(los);
    float nv  = expf(lno) + JIT;
    float c0  = -0.5f / ls2;

    // load X padded + y
    if (tid < TN) {
        int i = tid;
        float v[8];
#pragma unroll
        for (int d = 0; d < DDIM; ++d) v[d] = Xs[i * DDIM + d];
        v[6] = 0.f; v[7] = 0.f;
        float4* dst = (float4*)&sXp[i * 8];
        dst[0] = make_float4(v[0], v[1], v[2], v[3]);
        dst[1] = make_float4(v[4], v[5], v[6], v[7]);
        sW[i] = Ys[i];
    }
    __syncthreads();

    // ---- build K ----
    {
        int row  = tid & 255;
        int half = tid >> 8;
        const float4* X4 = (const float4*)sXp;
        float4 xi0 = X4[row * 2], xi1 = X4[row * 2 + 1];
        int jmid = (row + 1) >> 1;
        int jlo = half ? jmid : 0;
        int jhi = half ? (row + 1) : jmid;
        int idx = cpidx(jlo) + row - jlo;
        for (int j = jlo; j < jhi; ++j) {
            float4 xj0 = X4[j * 2], xj1 = X4[j * 2 + 1];
            float t0 = xi0.x - xj0.x, t1 = xi0.y - xj0.y, t2 = xi0.z - xj0.z, t3 = xi0.w - xj0.w;
            float t4 = xi1.x - xj1.x, t5 = xi1.y - xj1.y;
            float d2 = t0*t0 + t1*t1 + t2*t2 + t3*t3 + t4*t4 + t5*t5;
            float kv = (j == row) ? (osv + nv) : (osv * __expf(c0 * d2));
            sA[idx] = kv;
            idx += 255 - j;
        }
    }
    __syncthreads();

    const float4* pan4 = (const float4*)sPan;

    // ---- blocked Cholesky, panel width 8 ----
    for (int q = 0; q < 32; ++q) {
        int j0   = q * 8;
        int base = j0 + 8;
        int R    = TN - base;

        if (tid < TN) {
            float Ld[8][8];
            float dinv[8];
#pragma unroll
            for (int c = 0; c < 8; ++c) {
                int bidx = cpidx(j0 + c);
#pragma unroll
                for (int r = 0; r < 8; ++r)
                    if (r >= c) Ld[r][c] = sA[bidx + (r - c)];
            }
#pragma unroll
            for (int c = 0; c < 8; ++c) {
                float dsq = Ld[c][c];
#pragma unroll
                for (int p = 0; p < 8; ++p) if (p < c) dsq -= Ld[c][p] * Ld[c][p];
                float dl = sqrtf(dsq);
                Ld[c][c] = dl;
                float inv = 1.0f / dl;
                dinv[c] = inv;
#pragma unroll
                for (int r = 0; r < 8; ++r) {
                    if (r > c) {
                        float v = Ld[r][c];
#pragma unroll
                        for (int p = 0; p < 8; ++p) if (p < c) v -= Ld[r][p] * Ld[c][p];
                        Ld[r][c] = v * inv;
                    }
                }
            }
            if (tid < R) {
                int i = base + tid;
                float a[8];
#pragma unroll
                for (int c = 0; c < 8; ++c) a[c] = sA[cpidx(j0 + c) + (i - (j0 + c))];
#pragma unroll
                for (int c = 0; c < 8; ++c) {
                    float v = a[c];
#pragma unroll
                    for (int p = 0; p < 8; ++p) if (p < c) v -= a[p] * Ld[c][p];
                    a[c] = v * dinv[c];
                }
#pragma unroll
                for (int c = 0; c < 8; ++c) sA[cpidx(j0 + c) + (i - (j0 + c))] = a[c];
                float4* sp = (float4*)&sPan[tid * 8];
                sp[0] = make_float4(a[0], a[1], a[2], a[3]);
                sp[1] = make_float4(a[4], a[5], a[6], a[7]);
            }
#pragma unroll
            for (int r = 0; r < 8; ++r) {
                if (tid == r) {
#pragma unroll
                    for (int c = 0; c < 8; ++c)
                        if (c <= r) sA[cpidx(j0 + c) + (r - c)] = Ld[r][c];
                }
            }
        }
        __syncthreads();

        // ---- SYRK: warp per 8-row tile, panel rows in registers ----
        if (R > 0) {
            int nt = (R + 7) >> 3;
            for (int rt = wid; rt < nt; rt += 16) {
                int r0 = rt << 3;
                float4 pi0[8], pi1[8];
#pragma unroll
                for (int rr = 0; rr < 8; ++rr) {
                    if (r0 + rr < R) {
                        pi0[rr] = pan4[(r0 + rr) * 2];
                        pi1[rr] = pan4[(r0 + rr) * 2 + 1];
                    } else {
                        pi0[rr] = make_float4(0.f, 0.f, 0.f, 0.f);
                        pi1[rr] = make_float4(0.f, 0.f, 0.f, 0.f);
                    }
                }
                int rmax = min(r0 + 7, R - 1);
                for (int kb = 0; kb <= rmax; kb += 32) {
                    int kk = kb + lane;
                    float4 q0 = make_float4(0.f, 0.f, 0.f, 0.f);
                    float4 q1 = q0;
                    if (kk <= rmax) {
                        q0 = pan4[kk * 2];
                        q1 = pan4[kk * 2 + 1];
                    }
                    int c = base + kk;
                    int cbase = c * TN - ((c * (c - 1)) >> 1);
#pragma unroll
                    for (int rr = 0; rr < 8; ++rr) {
                        int rho = r0 + rr;
                        if (kk <= rho && rho < R) {
                            int idx = cbase + (rho - kk);
                            float v = sA[idx];
                            v -= pi0[rr].x*q0.x + pi0[rr].y*q0.y + pi0[rr].z*q0.z + pi0[rr].w*q0.w
                               + pi1[rr].x*q1.x + pi1[rr].y*q1.y + pi1[rr].z*q1.z + pi1[rr].w*q1.w;
                            sA[idx] = v;
                        }
                    }
                }
            }
        }
        __syncthreads();
    }

    // ---- inverse diagonal into sXp ----
    if (tid < TN) sXp[tid] = 1.0f / sA[cpidx(tid)];
    __syncthreads();

    // ---- concurrent epilogue: warp0 w-solve | warps1-8 Dinv | warps9-15 export L ----
    if (wid == 0) {
#pragma unroll 1
        for (int T = 0; T < 8; ++T) {
            int r = 32 * T + lane;
            float acc = sW[r];
            int lim = 32 * T;
            float a0 = 0.f, a1 = 0.f, a2 = 0.f, a3 = 0.f;
            int idx = r;
            for (int c = 0; c < lim; c += 4) {
                float z0 = sW[c], z1 = sW[c+1], z2 = sW[c+2], z3 = sW[c+3];
                float l0 = sA[idx]; idx += 255 - c;
                float l1 = sA[idx]; idx += 254 - c;
                float l2 = sA[idx]; idx += 253 - c;
                float l3 = sA[idx]; idx += 252 - c;
                a0 += l0 * z0; a1 += l1 * z1; a2 += l2 * z2; a3 += l3 * z3;
            }
            acc -= (a0 + a1) + (a2 + a3);
            float invv = sXp[r];
            int cb = 32 * T;
            float myz = 0.f;
#pragma unroll
            for (int s = 0; s < 32; ++s) {
                float zc = __shfl_sync(0xffffffffu, acc, s) * __shfl_sync(0xffffffffu, invv, s);
                if (lane == s) myz = zc;
                if (lane > s) acc -= sA[cpidx(cb + s) + (lane - s)] * zc;
            }
            sW[r] = myz;
            g_w[b * TN + r] = myz;
            __syncwarp();
        }
    } else if (wid <= 8) {
        int t = wid - 1;
        int s = lane;
        int c0t = 32 * t;
        float x[32];
#pragma unroll
        for (int r = 0; r < 32; ++r) {
            float sum = 0.f;
#pragma unroll
            for (int k = 0; k < 32; ++k) {
                if (k < r) sum += sA[cpidx(c0t + k) + (r - k)] * x[k];
            }
            float ivr = sXp[c0t + r];
            x[r] = (r == s) ? ivr : -sum * ivr;
        }
        float* dst = g_dinv + (size_t)b * 8192 + t * 1024 + s * 32;
#pragma unroll
        for (int r = 0; r < 32; ++r) dst[r] = x[r];
    } else {
        const float4* s4 = (const float4*)sA;
        float4* d4 = (float4*)(g_L + (size_t)b * PACK);
        for (int i = tid - 288; i < PACK / 4; i += 224) d4[i] = s4[i];
    }
}

// ---------------- kernel 3: per-problem prediction from smem-staged L ----------------
// smem (floats): sL[PACK] | sDv[8192] | sXp[2048] | sW[256] | sZ[2*16*256]
#define PSMEM_FLOATS (PACK + 8192 + 2048 + 256 + 8192)

__global__ void __launch_bounds__(512, 1) k_predict(
    const float* __restrict__ Xt,
    const float* __restrict__ X_exp, const float* __restrict__ X_base,
    const float* __restrict__ lls_e, const float* __restrict__ los_e, const float* __restrict__ lno_e,
    const float* __restrict__ lls_b, const float* __restrict__ los_b, const float* __restrict__ lno_b)
{
    int b = blockIdx.x;
    int cnt = g_cnt[b];
    if (cnt == 0) return;

    extern __shared__ float sm[];
    float* sL  = sm;
    float* sDv = sL  + PACK;
    float* sXp = sDv + 8192;
    float* sW  = sXp + 2048;
    float* sZ  = sW  + 256;

    int tid  = threadIdx.x;
    int wid  = tid >> 5;
    int lane = tid & 31;

    const float* Xs; float lls, los, lno;
    if (b < NEXP) {
        Xs = X_exp + (size_t)b * TN * DDIM;
        lls = lls_e[b]; los = los_e[b]; lno = lno_e[b];
    } else {
        int gb = b - NEXP;
        Xs = X_base + (size_t)gb * TN * DDIM;
        lls = lls_b[gb]; los = los_b[gb]; lno = lno_b[gb];
    }
    float ls2 = expf(2.f * lls);
    float osv = expf(los);
    float nv  = expf(lno) + JIT;
    float c0  = -0.5f / ls2;

    // stage L, Dinv (float4 coalesced), Xtr padded, w
    {
        const float4* s4 = (const float4*)(g_L + (size_t)b * PACK);
        float4* d4 = (float4*)sL;
        for (int i = tid; i < PACK / 4; i += 512) d4[i] = s4[i];
        const float4* dv4 = (const float4*)(g_dinv + (size_t)b * 8192);
        float4* dd4 = (float4*)sDv;
        for (int i = tid; i < 2048; i += 512) dd4[i] = dv4[i];
        if (tid < TN) {
            float v[8];
#pragma unroll
            for (int d = 0; d < DDIM; ++d) v[d] = Xs[tid * DDIM + d];
            v[6] = 0.f; v[7] = 0.f;
            float4* dst = (float4*)&sXp[tid * 8];
            dst[0] = make_float4(v[0], v[1], v[2], v[3]);
            dst[1] = make_float4(v[4], v[5], v[6], v[7]);
            sW[tid] = g_w[b * TN + tid];
        }
    }
    __syncthreads();

    const int* pts = g_pts + (size_t)b * NTEST;
    float* z0 = sZ + wid * 512;
    float* z1 = z0 + 256;

    // two points per warp per round; L/Dinv loads shared between them
    for (int pi = wid * 2; pi < cnt; pi += 32) {
        int n0 = pts[pi];
        bool has1 = (pi + 1 < cnt);
        int n1 = has1 ? pts[pi + 1] : n0;

        float x00 = Xt[n0*DDIM+0], x01 = Xt[n0*DDIM+1], x02 = Xt[n0*DDIM+2];
        float x03 = Xt[n0*DDIM+3], x04 = Xt[n0*DDIM+4], x05 = Xt[n0*DDIM+5];
        float x10 = Xt[n1*DDIM+0], x11 = Xt[n1*DDIM+1], x12 = Xt[n1*DDIM+2];
        float x13 = Xt[n1*DDIM+3], x14 = Xt[n1*DDIM+4], x15 = Xt[n1*DDIM+5];

        float qq0 = 0.f, mu0 = 0.f, qq1 = 0.f, mu1 = 0.f;
#pragma unroll 1
        for (int T = 0; T < 8; ++T) {
            int r  = 32 * T + lane;
            int cb = 32 * T;
            float4 xr0 = ((const float4*)&sXp[r * 8])[0];
            float4 xr1 = ((const float4*)&sXp[r * 8])[1];
            float t0 = x00 - xr0.x, t1 = x01 - xr0.y, t2 = x02 - xr0.z;
            float t3 = x03 - xr0.w, t4 = x04 - xr1.x, t5 = x05 - xr1.y;
            float d2a = t0*t0 + t1*t1 + t2*t2 + t3*t3 + t4*t4 + t5*t5;
            t0 = x10 - xr0.x; t1 = x11 - xr0.y; t2 = x12 - xr0.z;
            t3 = x13 - xr0.w; t4 = x14 - xr1.x; t5 = x15 - xr1.y;
            float d2b = t0*t0 + t1*t1 + t2*t2 + t3*t3 + t4*t4 + t5*t5;
            float acc0 = osv * __expf(c0 * d2a);
            float acc1 = osv * __expf(c0 * d2b);

            // GEMV vs previous z tiles; L loads shared across the 2 points
            float p00 = 0.f, p01 = 0.f, p02 = 0.f, p03 = 0.f;
            float p10 = 0.f, p11 = 0.f, p12 = 0.f, p13 = 0.f;
            int idx = r;
#pragma unroll 2
            for (int c = 0; c < cb; c += 4) {
                float4 za = *(const float4*)&z0[c];
                float4 zb = *(const float4*)&z1[c];
                float l0 = sL[idx]; idx += 255 - c;
                float l1 = sL[idx]; idx += 254 - c;
                float l2 = sL[idx]; idx += 253 - c;
                float l3 = sL[idx]; idx += 252 - c;
                p00 += l0 * za.x; p10 += l0 * zb.x;
                p01 += l1 * za.y; p11 += l1 * zb.y;
                p02 += l2 * za.z; p12 += l2 * zb.z;
                p03 += l3 * za.w; p13 += l3 * zb.w;
            }
            acc0 -= (p00 + p01) + (p02 + p03);
            acc1 -= (p10 + p11) + (p12 + p13);

            // v = Dinv * acc : Dt loads shared across the 2 points
            const float* Dt = sDv + T * 1024;
            float v00 = 0.f, v01 = 0.f, v02 = 0.f, v03 = 0.f;
            float v10 = 0.f, v11 = 0.f, v12 = 0.f, v13 = 0.f;
#pragma unroll
            for (int s = 0; s < 32; s += 4) {
                float d0 = Dt[(s+0) * 32 + lane];
                float d1 = Dt[(s+1) * 32 + lane];
                float d2 = Dt[(s+2) * 32 + lane];
                float d3 = Dt[(s+3) * 32 + lane];
                float b00 = __shfl_sync(0xffffffffu, acc0, s+0);
                float b01 = __shfl_sync(0xffffffffu, acc0, s+1);
                float b02 = __shfl_sync(0xffffffffu, acc0, s+2);
                float b03 = __shfl_sync(0xffffffffu, acc0, s+3);
                float b10 = __shfl_sync(0xffffffffu, acc1, s+0);
                float b11 = __shfl_sync(0xffffffffu, acc1, s+1);
                float b12 = __shfl_sync(0xffffffffu, acc1, s+2);
                float b13 = __shfl_sync(0xffffffffu, acc1, s+3);
                v00 += d0 * b00; v10 += d0 * b10;
                v01 += d1 * b01; v11 += d1 * b11;
                v02 += d2 * b02; v12 += d2 * b12;
                v03 += d3 * b03; v13 += d3 * b13;
            }
            float v0 = (v00 + v01) + (v02 + v03);
            float v1 = (v10 + v11) + (v12 + v13);
            z0[r] = v0;
            z1[r] = v1;
            float wr = sW[r];
            qq0 += v0 * v0;  mu0 += v0 * wr;
            qq1 += v1 * v1;  mu1 += v1 * wr;
            __syncwarp();
        }

#pragma unroll
        for (int o = 16; o; o >>= 1) {
            mu0 += __shfl_xor_sync(0xffffffffu, mu0, o);
            qq0 += __shfl_xor_sync(0xffffffffu, qq0, o);
            mu1 += __shfl_xor_sync(0xffffffffu, mu1, o);
            qq1 += __shfl_xor_sync(0xffffffffu, qq1, o);
        }
        if (lane == 0) {
            float prior = osv + nv;
            float var0 = fmaxf(osv - qq0, JIT) + nv;
            if (b < NEXP) { g_mu_e[n0] = mu0; g_var_e[n0] = var0; g_prior_e[n0] = prior; }
            else          { g_mu_b[n0] = mu0; g_var_b[n0] = var0; g_prior_b[n0] = prior; }
            if (has1) {
                float var1 = fmaxf(osv - qq1, JIT) + nv;
                if (b < NEXP) { g_mu_e[n1] = mu1; g_var_e[n1] = var1; g_prior_e[n1] = prior; }
                else          { g_mu_b[n1] = mu1; g_var_b[n1] = var1; g_prior_b[n1] = prior; }
            }
        }
    }
}

// ---------------- kernel 4: rBCM combine ----------------
__global__ void k_combine(const int* __restrict__ nmask, float* __restrict__ out)
{
    int n = blockIdx.x * blockDim.x + threadIdx.x;
    if (n >= NTEST) return;
    int e = g_route_e[n];
    bool isnull = (nmask[e] == 0);
    float mub = g_mu_b[n], varb = g_var_b[n], prb = g_prior_b[n];
    float bb = fmaxf(0.5f * (logf(prb) - logf(varb)), 0.f);
    float be = 0.f, te = 0.f, me = 0.f;
    if (!isnull) {
        float mue = g_mu_e[n], vare = g_var_e[n], pre = g_prior_e[n];
        be = fmaxf(0.5f * (logf(pre) - logf(vare)), 0.f);
        te = be / vare;
        me = be * mue / vare;
    }
    float prec = te + bb / varb + (1.f - be - bb) / prb;
    prec = fmaxf(prec, 1e-6f);
    float mean = (me + bb * mub / varb) / prec;
    out[n] = mean;
    out[NTEST + n] = 1.f / prec;
}

// ---------------- launch ----------------
extern "C" void kernel_launch(void* const* d_in, const int* in_sizes, int n_in,
                              void* d_out, int out_size)
{
    const float* X_test   = (const float*)d_in[0];
    const float* X_exp    = (const float*)d_in[1];
    const float* Y_exp    = (const float*)d_in[2];
    const float* X_base   = (const float*)d_in[3];
    const float* Y_base   = (const float*)d_in[4];
    const float* lls_e    = (const float*)d_in[5];
    const float* los_e    = (const float*)d_in[6];
    const float* lno_e    = (const float*)d_in[7];
    const float* lls_b    = (const float*)d_in[8];
    const float* los_b    = (const float*)d_in[9];
    const float* lno_b    = (const float*)d_in[10];
    const float* smean    = (const float*)d_in[11];
    const float* sscale   = (const float*)d_in[12];
    const float* gm       = (const float*)d_in[13];
    const float* glv      = (const float*)d_in[14];
    const float* glw      = (const float*)d_in[15];
    const float* pm       = (const float*)d_in[16];
    const float* plv      = (const float*)d_in[17];
    const float* plw      = (const float*)d_in[18];
    const int*   nmask    = (const int*)d_in[19];
    float* out = (float*)d_out;

    static_assert(SMEM_FLOATS  * 4 <= 232448, "smem factor");
    static_assert(PSMEM_FLOATS * 4 <= 232448, "smem predict");
    cudaFuncSetAttribute(k_factor, cudaFuncAttributeMaxDynamicSharedMemorySize,
                         SMEM_FLOATS * 4);
    cudaFuncSetAttribute(k_predict, cudaFuncAttributeMaxDynamicSharedMemorySize,
                         PSMEM_FLOATS * 4);

    k_zero<<<(NPROB + 255) / 256, 256>>>();
    k_route<<<(NTEST + 255) / 256, 256>>>(X_test, smean, sscale, gm, glv, glw,
                                          pm, plv, plw, nmask);
    k_factor<<<NPROB, 512, SMEM_FLOATS * 4>>>(X_exp, Y_exp, X_base, Y_base,
                                              lls_e, los_e, lno_e,
                                              lls_b, los_b, lno_b);
    k_predict<<<NPROB, 512, PSMEM_FLOATS * 4>>>(X_test, X_exp, X_base,
                                                lls_e, los_e, lno_e,
                                                lls_b, los_b, lno_b);
    k_combine<<<(NTEST + 255) / 256, 256>>>(nmask, out);
}

// round 7
// speedup vs baseline: 3.0785x; 2.4110x over previous
#include <cuda_runtime.h>
#include <cuda_bf16.h>
#include <math.h>

#define TN     256
#define DDIM   6
#define NEXP   540
#define NGEO   20
#define KPHI   27
#define NPROB  560          // 540 experts + 20 baselines
#define NTEST  1024
#define PACK   32896        // 256*257/2
#define JIT    1e-4f

// ---------------- static device scratch ----------------
__device__ float g_L[(size_t)NPROB * PACK];           // packed column-major lower L
__device__ float g_w[NPROB * TN];                     // w = L^-1 y
__device__ float g_dinv[(size_t)NPROB * 8 * 32 * 32]; // per-tile 32x32 diag-block inverses [tile][s][r]
__device__ int   g_used[NPROB];
__device__ int   g_route_e[NTEST];
__device__ int   g_route_g[NTEST];
__device__ float g_mu_e[NTEST],  g_var_e[NTEST],  g_prior_e[NTEST];
__device__ float g_mu_b[NTEST],  g_var_b[NTEST],  g_prior_b[NTEST];

__device__ __forceinline__ int cpidx(int j) { return j * TN - ((j * (j - 1)) >> 1); }

// ---------------- kernel 0: clear used flags ----------------
__global__ void k_zero() {
    int i = blockIdx.x * blockDim.x + threadIdx.x;
    if (i < NPROB) g_used[i] = 0;
}

// ---------------- kernel 1: 2-level GMM routing ----------------
__global__ void k_route(const float* __restrict__ Xt,
                        const float* __restrict__ smean, const float* __restrict__ sscale,
                        const float* __restrict__ gm,    const float* __restrict__ glv,
                        const float* __restrict__ glw,
                        const float* __restrict__ pm,    const float* __restrict__ plv,
                        const float* __restrict__ plw,
                        const int*   __restrict__ nmask)
{
    int n = blockIdx.x * blockDim.x + threadIdx.x;
    if (n >= NTEST) return;
    float xs[DDIM];
#pragma unroll
    for (int d = 0; d < DDIM; ++d) xs[d] = (Xt[n * DDIM + d] - smean[d]) / sscale[d];

    float best = -3e38f; int gb = 0;
    for (int gi = 0; gi < NGEO; ++gi) {
        float acc = 0.f;
#pragma unroll
        for (int d = 0; d < DDIM; ++d) {
            float lv = glv[gi * DDIM + d];
            float t  = xs[d] - gm[gi * DDIM + d];
            acc += lv + t * t * expf(-lv);
        }
        float lp = glw[gi] - 0.5f * acc;
        if (lp > best) { best = lp; gb = gi; }
    }
    float bestp = -3e38f; int kb = 0;
    for (int kk = 0; kk < KPHI; ++kk) {
        int base = (gb * KPHI + kk) * DDIM;
        float acc = 0.f;
#pragma unroll
        for (int d = 0; d < DDIM; ++d) {
            float lv = plv[base + d];
            float t  = xs[d] - pm[base + d];
            acc += lv + t * t * expf(-lv);
        }
        float lp = plw[gb * KPHI + kk] - 0.5f * acc;
        if (lp > bestp) { bestp = lp; kb = kk; }
    }
    int e = gb * KPHI + kb;
    g_route_e[n] = e;
    g_route_g[n] = gb;
    if (nmask[e] != 0) g_used[e] = 1;
    g_used[NEXP + gb] = 1;
}

// ---------------- kernel 2: build K, blocked Cholesky, Dinv, w-solve, export ----------------
// smem (floats): sA[PACK] | sXp[256*8] | sPan[256*8] | sW[256]
#define SMEM_FLOATS (PACK + TN*8 + TN*8 + TN)

__global__ void __launch_bounds__(512, 1) k_factor(
    const float* __restrict__ X_exp,  const float* __restrict__ Y_exp,
    const float* __restrict__ X_base, const float* __restrict__ Y_base,
    const float* __restrict__ lls_e, const float* __restrict__ los_e, const float* __restrict__ lno_e,
    const float* __restrict__ lls_b, const float* __restrict__ los_b, const float* __restrict__ lno_b)
{
    int b = blockIdx.x;
    if (!g_used[b]) return;

    extern __shared__ float sm[];
    float* sA   = sm;
    float* sXp  = sA + PACK;       // X padded [256][8]; later reused for inv-diag
    float* sPan = sXp + TN * 8;    // panel rows [256][8]
    float* sW   = sPan + TN * 8;   // y -> w

    int tid  = threadIdx.x;
    int wid  = tid >> 5;
    int lane = tid & 31;

    const float* Xs; const float* Ys; float lls, los, lno;
    if (b < NEXP) {
        Xs = X_exp + (size_t)b * TN * DDIM;  Ys = Y_exp + b * TN;
        lls = lls_e[b]; los = los_e[b]; lno = lno_e[b];
    } else {
        int gb = b - NEXP;
        Xs = X_base + (size_t)gb * TN * DDIM; Ys = Y_base + gb * TN;
        lls = lls_b[gb]; los = los_b[gb]; lno = lno_b[gb];
    }
    float ls2 = expf(2.f * lls);
    float osv = expf(los);
    float nv  = expf(lno) + JIT;
    float c0  = -0.5f / ls2;

    if (tid < TN) {
        int i = tid;
        float v[8];
#pragma unroll
        for (int d = 0; d < DDIM; ++d) v[d] = Xs[i * DDIM + d];
        v[6] = 0.f; v[7] = 0.f;
        float4* dst = (float4*)&sXp[i * 8];
        dst[0] = make_float4(v[0], v[1], v[2], v[3]);
        dst[1] = make_float4(v[4], v[5], v[6], v[7]);
        sW[i] = Ys[i];
    }
    __syncthreads();

    // ---- build K ----
    {
        int row  = tid & 255;
        int half = tid >> 8;
        const float4* X4 = (const float4*)sXp;
        float4 xi0 = X4[row * 2], xi1 = X4[row * 2 + 1];
        int jmid = (row + 1) >> 1;
        int jlo = half ? jmid : 0;
        int jhi = half ? (row + 1) : jmid;
        int idx = cpidx(jlo) + row - jlo;
        for (int j = jlo; j < jhi; ++j) {
            float4 xj0 = X4[j * 2], xj1 = X4[j * 2 + 1];
            float t0 = xi0.x - xj0.x, t1 = xi0.y - xj0.y, t2 = xi0.z - xj0.z, t3 = xi0.w - xj0.w;
            float t4 = xi1.x - xj1.x, t5 = xi1.y - xj1.y;
            float d2 = t0*t0 + t1*t1 + t2*t2 + t3*t3 + t4*t4 + t5*t5;
            float kv = (j == row) ? (osv + nv) : (osv * __expf(c0 * d2));
            sA[idx] = kv;
            idx += 255 - j;
        }
    }
    __syncthreads();

    const float4* pan4 = (const float4*)sPan;

    // ---- blocked Cholesky, panel width 8 ----
    for (int q = 0; q < 32; ++q) {
        int j0   = q * 8;
        int base = j0 + 8;
        int R    = TN - base;

        if (tid < TN) {
            float Ld[8][8];
            float dinv[8];
#pragma unroll
            for (int c = 0; c < 8; ++c) {
                int bidx = cpidx(j0 + c);
#pragma unroll
                for (int r = 0; r < 8; ++r)
                    if (r >= c) Ld[r][c] = sA[bidx + (r - c)];
            }
#pragma unroll
            for (int c = 0; c < 8; ++c) {
                float dsq = Ld[c][c];
#pragma unroll
                for (int p = 0; p < 8; ++p) if (p < c) dsq -= Ld[c][p] * Ld[c][p];
                float dl = sqrtf(dsq);
                Ld[c][c] = dl;
                float inv = 1.0f / dl;
                dinv[c] = inv;
#pragma unroll
                for (int r = 0; r < 8; ++r) {
                    if (r > c) {
                        float v = Ld[r][c];
#pragma unroll
                        for (int p = 0; p < 8; ++p) if (p < c) v -= Ld[r][p] * Ld[c][p];
                        Ld[r][c] = v * inv;
                    }
                }
            }
            if (tid < R) {
                int i = base + tid;
                float a[8];
#pragma unroll
                for (int c = 0; c < 8; ++c) a[c] = sA[cpidx(j0 + c) + (i - (j0 + c))];
#pragma unroll
                for (int c = 0; c < 8; ++c) {
                    float v = a[c];
#pragma unroll
                    for (int p = 0; p < 8; ++p) if (p < c) v -= a[p] * Ld[c][p];
                    a[c] = v * dinv[c];
                }
#pragma unroll
                for (int c = 0; c < 8; ++c) sA[cpidx(j0 + c) + (i - (j0 + c))] = a[c];
                float4* sp = (float4*)&sPan[tid * 8];
                sp[0] = make_float4(a[0], a[1], a[2], a[3]);
                sp[1] = make_float4(a[4], a[5], a[6], a[7]);
            }
#pragma unroll
            for (int r = 0; r < 8; ++r) {
                if (tid == r) {
#pragma unroll
                    for (int c = 0; c < 8; ++c)
                        if (c <= r) sA[cpidx(j0 + c) + (r - c)] = Ld[r][c];
                }
            }
        }
        __syncthreads();

        if (R > 0) {
            int nt = (R + 7) >> 3;
            for (int rt = wid; rt < nt; rt += 16) {
                int r0 = rt << 3;
                float4 pi0[8], pi1[8];
#pragma unroll
                for (int rr = 0; rr < 8; ++rr) {
                    if (r0 + rr < R) {
                        pi0[rr] = pan4[(r0 + rr) * 2];
                        pi1[rr] = pan4[(r0 + rr) * 2 + 1];
                    } else {
                        pi0[rr] = make_float4(0.f, 0.f, 0.f, 0.f);
                        pi1[rr] = make_float4(0.f, 0.f, 0.f, 0.f);
                    }
                }
                int rmax = min(r0 + 7, R - 1);
                for (int kb = 0; kb <= rmax; kb += 32) {
                    int kk = kb + lane;
                    float4 q0 = make_float4(0.f, 0.f, 0.f, 0.f);
                    float4 q1 = q0;
                    if (kk <= rmax) {
                        q0 = pan4[kk * 2];
                        q1 = pan4[kk * 2 + 1];
                    }
                    int c = base + kk;
                    int cbase = c * TN - ((c * (c - 1)) >> 1);
#pragma unroll
                    for (int rr = 0; rr < 8; ++rr) {
                        int rho = r0 + rr;
                        if (kk <= rho && rho < R) {
                            int idx = cbase + (rho - kk);
                            float v = sA[idx];
                            v -= pi0[rr].x*q0.x + pi0[rr].y*q0.y + pi0[rr].z*q0.z + pi0[rr].w*q0.w
                               + pi1[rr].x*q1.x + pi1[rr].y*q1.y + pi1[rr].z*q1.z + pi1[rr].w*q1.w;
                            sA[idx] = v;
                        }
                    }
                }
            }
        }
        __syncthreads();
    }

    if (tid < TN) sXp[tid] = 1.0f / sA[cpidx(tid)];
    __syncthreads();

    // ---- concurrent epilogue: warp0 w-solve | warps1-8 Dinv | warps9-15 export L ----
    if (wid == 0) {
#pragma unroll 1
        for (int T = 0; T < 8; ++T) {
            int r = 32 * T + lane;
            float acc = sW[r];
            int lim = 32 * T;
            float a0 = 0.f, a1 = 0.f, a2 = 0.f, a3 = 0.f;
            int idx = r;
            for (int c = 0; c < lim; c += 4) {
                float z0 = sW[c], z1 = sW[c+1], z2 = sW[c+2], z3 = sW[c+3];
                float l0 = sA[idx]; idx += 255 - c;
                float l1 = sA[idx]; idx += 254 - c;
                float l2 = sA[idx]; idx += 253 - c;
                float l3 = sA[idx]; idx += 252 - c;
                a0 += l0 * z0; a1 += l1 * z1; a2 += l2 * z2; a3 += l3 * z3;
            }
            acc -= (a0 + a1) + (a2 + a3);
            float invv = sXp[r];
            int cb = 32 * T;
            float myz = 0.f;
#pragma unroll
            for (int s = 0; s < 32; ++s) {
                float zc = __shfl_sync(0xffffffffu, acc, s) * __shfl_sync(0xffffffffu, invv, s);
                if (lane == s) myz = zc;
                if (lane > s) acc -= sA[cpidx(cb + s) + (lane - s)] * zc;
            }
            sW[r] = myz;
            g_w[b * TN + r] = myz;
            __syncwarp();
        }
    } else if (wid <= 8) {
        int t = wid - 1;
        int s = lane;
        int c0t = 32 * t;
        float x[32];
#pragma unroll
        for (int r = 0; r < 32; ++r) {
            float sum = 0.f;
#pragma unroll
            for (int k = 0; k < 32; ++k) {
                if (k < r) sum += sA[cpidx(c0t + k) + (r - k)] * x[k];
            }
            float ivr = sXp[c0t + r];
            x[r] = (r == s) ? ivr : -sum * ivr;
        }
        float* dst = g_dinv + (size_t)b * 8192 + t * 1024 + s * 32;
#pragma unroll
        for (int r = 0; r < 32; ++r) dst[r] = x[r];
    } else {
        const float4* s4 = (const float4*)sA;
        float4* d4 = (float4*)(g_L + (size_t)b * PACK);
        for (int i = tid - 288; i < PACK / 4; i += 224) d4[i] = s4[i];
    }
}

// ---------------- kernel 3: point-major prediction, block-per-task, row-per-thread ----------------
__global__ void __launch_bounds__(256) k_predict(
    const float* __restrict__ Xt,
    const float* __restrict__ X_exp, const float* __restrict__ X_base,
    const float* __restrict__ lls_e, const float* __restrict__ los_e, const float* __restrict__ lno_e,
    const float* __restrict__ lls_b, const float* __restrict__ los_b, const float* __restrict__ lno_b,
    const int*   __restrict__ nmask)
{
    __shared__ float sZ[TN];
    __shared__ float sRed[16];

    int task = blockIdx.x;            // 0..2047
    int n = task >> 1;
    bool is_base = (task & 1);

    int p; const float* Xtr; float lls, los, lno;
    if (!is_base) {
        int e = g_route_e[n];
        if (nmask[e] == 0) return;    // k_combine never reads expert slots for null
        p = e; Xtr = X_exp + (size_t)e * TN * DDIM;
        lls = lls_e[e]; los = los_e[e]; lno = lno_e[e];
    } else {
        int g = g_route_g[n];
        p = NEXP + g; Xtr = X_base + (size_t)g * TN * DDIM;
        lls = lls_b[g]; los = los_b[g]; lno = lno_b[g];
    }
    float ls2 = expf(2.f * lls);
    float osv = expf(los);
    float nv  = expf(lno) + JIT;
    float c0  = -0.5f / ls2;

    int r    = threadIdx.x;           // row 0..255
    int wid  = r >> 5;
    int lane = r & 31;

    // k*(x_n, Xtr[r]) -> initial residual acc
    float acc;
    {
        float d2 = 0.f;
#pragma unroll
        for (int d = 0; d < DDIM; ++d) {
            float tv = Xt[n * DDIM + d] - Xtr[r * DDIM + d];
            d2 += tv * tv;
        }
        acc = osv * __expf(c0 * d2);
    }
    float wr = g_w[p * TN + r];

    const float* Lp = g_L    + (size_t)p * PACK;
    const float* Dv = g_dinv + (size_t)p * 8192;

    // right-looking block forward solve: 8 steps
#pragma unroll
    for (int T = 0; T < 8; ++T) {
        if (wid == T) {
            // z_tile = Dinv_T * acc_tile (coalesced L2 loads, shfl broadcast)
            const float* Dt = Dv + T * 1024;
            float v0 = 0.f, v1 = 0.f, v2 = 0.f, v3 = 0.f;
#pragma unroll
            for (int s = 0; s < 32; s += 4) {
                float d0 = Dt[(s+0) * 32 + lane];
                float d1 = Dt[(s+1) * 32 + lane];
                float d2 = Dt[(s+2) * 32 + lane];
                float d3 = Dt[(s+3) * 32 + lane];
                float b0 = __shfl_sync(0xffffffffu, acc, s+0);
                float b1 = __shfl_sync(0xffffffffu, acc, s+1);
                float b2 = __shfl_sync(0xffffffffu, acc, s+2);
                float b3 = __shfl_sync(0xffffffffu, acc, s+3);
                v0 += d0 * b0; v1 += d1 * b1; v2 += d2 * b2; v3 += d3 * b3;
            }
            sZ[r] = (v0 + v1) + (v2 + v3);
        }
        __syncthreads();
        if (T < 7 && wid > T) {
            // acc -= L[cols 32T..32T+31][row r] . z_tile  (32 independent coalesced loads)
            int c0i = 32 * T;
            int idx = c0i * TN - ((c0i * (c0i - 1)) >> 1) + (r - c0i);
            float a0 = 0.f, a1 = 0.f, a2 = 0.f, a3 = 0.f;
#pragma unroll
            for (int j = 0; j < 8; ++j) {
                int c = c0i + j * 4;
                float z0 = sZ[c], z1 = sZ[c+1], z2 = sZ[c+2], z3 = sZ[c+3];
                float l0 = Lp[idx]; idx += 255 - c;
                float l1 = Lp[idx]; idx += 254 - c;
                float l2 = Lp[idx]; idx += 253 - c;
                float l3 = Lp[idx]; idx += 252 - c;
                a0 += l0 * z0; a1 += l1 * z1; a2 += l2 * z2; a3 += l3 * z3;
            }
            acc -= (a0 + a1) + (a2 + a3);
        }
    }

    // reduce qq = |z|^2, mu = z.w
    float z = sZ[r];
    float qq = z * z;
    float mu = z * wr;
#pragma unroll
    for (int o = 16; o; o >>= 1) {
        qq += __shfl_xor_sync(0xffffffffu, qq, o);
        mu += __shfl_xor_sync(0xffffffffu, mu, o);
    }
    if (lane == 0) { sRed[wid] = qq; sRed[8 + wid] = mu; }
    __syncthreads();
    if (r == 0) {
        float tq = 0.f, tm = 0.f;
#pragma unroll
        for (int i = 0; i < 8; ++i) { tq += sRed[i]; tm += sRed[8 + i]; }
        float var = fmaxf(osv - tq, JIT) + nv;
        float prior = osv + nv;
        if (!is_base) { g_mu_e[n] = tm; g_var_e[n] = var; g_prior_e[n] = prior; }
        else          { g_mu_b[n] = tm; g_var_b[n] = var; g_prior_b[n] = prior; }
    }
}

// ---------------- kernel 4: rBCM combine ----------------
__global__ void k_combine(const int* __restrict__ nmask, float* __restrict__ out)
{
    int n = blockIdx.x * blockDim.x + threadIdx.x;
    if (n >= NTEST) return;
    int e = g_route_e[n];
    bool isnull = (nmask[e] == 0);
    float mub = g_mu_b[n], varb = g_var_b[n], prb = g_prior_b[n];
    float bb = fmaxf(0.5f * (logf(prb) - logf(varb)), 0.f);
    float be = 0.f, te = 0.f, me = 0.f;
    if (!isnull) {
        float mue = g_mu_e[n], vare = g_var_e[n], pre = g_prior_e[n];
        be = fmaxf(0.5f * (logf(pre) - logf(vare)), 0.f);
        te = be / vare;
        me = be * mue / vare;
    }
    float prec = te + bb / varb + (1.f - be - bb) / prb;
    prec = fmaxf(prec, 1e-6f);
    float mean = (me + bb * mub / varb) / prec;
    out[n] = mean;
    out[NTEST + n] = 1.f / prec;
}

// ---------------- launch ----------------
extern "C" void kernel_launch(void* const* d_in, const int* in_sizes, int n_in,
                              void* d_out, int out_size)
{
    const float* X_test   = (const float*)d_in[0];
    const float* X_exp    = (const float*)d_in[1];
    const float* Y_exp    = (const float*)d_in[2];
    const float* X_base   = (const float*)d_in[3];
    const float* Y_base   = (const float*)d_in[4];
    const float* lls_e    = (const float*)d_in[5];
    const float* los_e    = (const float*)d_in[6];
    const float* lno_e    = (const float*)d_in[7];
    const float* lls_b    = (const float*)d_in[8];
    const float* los_b    = (const float*)d_in[9];
    const float* lno_b    = (const float*)d_in[10];
    const float* smean    = (const float*)d_in[11];
    const float* sscale   = (const float*)d_in[12];
    const float* gm       = (const float*)d_in[13];
    const float* glv      = (const float*)d_in[14];
    const float* glw      = (const float*)d_in[15];
    const float* pm       = (const float*)d_in[16];
    const float* plv      = (const float*)d_in[17];
    const float* plw      = (const float*)d_in[18];
    const int*   nmask    = (const int*)d_in[19];
    float* out = (float*)d_out;

    static_assert(SMEM_FLOATS * 4 <= 232448, "smem factor");
    cudaFuncSetAttribute(k_factor, cudaFuncAttributeMaxDynamicSharedMemorySize,
                         SMEM_FLOATS * 4);

    k_zero<<<(NPROB + 255) / 256, 256>>>();
    k_route<<<(NTEST + 255) / 256, 256>>>(X_test, smean, sscale, gm, glv, glw,
                                          pm, plv, plw, nmask);
    k_factor<<<NPROB, 512, SMEM_FLOATS * 4>>>(X_exp, Y_exp, X_base, Y_base,
                                              lls_e, los_e, lno_e,
                                              lls_b, los_b, lno_b);
    k_predict<<<2 * NTEST, 256>>>(X_test, X_exp, X_base,
                                  lls_e, los_e, lno_e,
                                  lls_b, los_b, lno_b, nmask);
    k_combine<<<(NTEST + 255) / 256, 256>>>(nmask, out);
}